// round 3
// baseline (speedup 1.0000x reference)
#include <cuda_runtime.h>
#include <cuda_fp16.h>
#include <math.h>
#include <stdint.h>

// Problem dims
#define SEQ    4096
#define IDIM   2048
#define HDIM   2048
#define GROWS  8192   // 4*HDIM, PyTorch gate order i,f,g,o
#define OUTD   2048

// Persistent recurrence kernel config
#define UPC      14            // hidden units per CTA
#define NCTA     147           // ceil(2048/14) -> 146 full + 1 partial, <= SM count (152)
#define RTHREADS 256
#define MAXROWS  (4*UPC)       // 56 gate rows per full CTA
#define SW_BYTES (MAXROWS*HDIM*sizeof(__half))  // 229376 B dynamic smem

// -------- device scratch (static allocation only; no cudaMalloc allowed) --------
__device__ float    g_xg[(size_t)SEQ * GROWS];  // 128 MB: precomputed x@W_ih^T + biases
__device__ float    g_h[2][HDIM];               // double-buffered hidden state
__device__ unsigned g_bar  = 0u;                // monotonic arrival counter
__device__ unsigned g_base = 0u;                // epoch base (updated at end of each launch)

// ============================================================================
// Kernel 1: xg[t][n] = sum_k x[t,k] * W_ih[n,k] + b_ih[n] + b_hh[n]
// Classic 128x128x8 register-tiled SGEMM (both operands K-major -> "NT" gemm).
// ============================================================================
__global__ void __launch_bounds__(256)
gemm_xg_kernel(const float* __restrict__ A,   // x      [SEQ][IDIM]
               const float* __restrict__ B,   // W_ih   [GROWS][IDIM]
               const float* __restrict__ b1,  // b_ih
               const float* __restrict__ b2)  // b_hh
{
    constexpr int BM = 128, BN = 128, BK = 8, K = IDIM;
    __shared__ float As[BK][BM];
    __shared__ float Bs[BK][BN];

    const int bm  = blockIdx.y * BM;
    const int bn  = blockIdx.x * BN;
    const int tid = threadIdx.x;

    // load mapping: one float4 per thread per tile per matrix
    const int lrow = tid >> 1;            // 0..127
    const int lk4  = (tid & 1) * 4;       // 0 or 4
    const float* Aptr = A + (size_t)(bm + lrow) * K + lk4;
    const float* Bptr = B + (size_t)(bn + lrow) * K + lk4;

    const int tx = tid & 15;              // 16 n-groups
    const int ty = tid >> 4;              // 16 m-groups

    float acc[8][8];
#pragma unroll
    for (int i = 0; i < 8; ++i)
#pragma unroll
        for (int j = 0; j < 8; ++j) acc[i][j] = 0.f;

    float4 pa = *(const float4*)Aptr;
    float4 pb = *(const float4*)Bptr;

    const int NT = K / BK;   // 256
    for (int kt = 0; kt < NT; ++kt) {
        As[lk4 + 0][lrow] = pa.x; As[lk4 + 1][lrow] = pa.y;
        As[lk4 + 2][lrow] = pa.z; As[lk4 + 3][lrow] = pa.w;
        Bs[lk4 + 0][lrow] = pb.x; Bs[lk4 + 1][lrow] = pb.y;
        Bs[lk4 + 2][lrow] = pb.z; Bs[lk4 + 3][lrow] = pb.w;
        __syncthreads();

        if (kt + 1 < NT) {
            pa = *(const float4*)(Aptr + (kt + 1) * BK);
            pb = *(const float4*)(Bptr + (kt + 1) * BK);
        }

#pragma unroll
        for (int k = 0; k < BK; ++k) {
            float a[8], b[8];
            *(float4*)&a[0] = *(const float4*)&As[k][ty * 8];
            *(float4*)&a[4] = *(const float4*)&As[k][ty * 8 + 4];
            *(float4*)&b[0] = *(const float4*)&Bs[k][tx * 8];
            *(float4*)&b[4] = *(const float4*)&Bs[k][tx * 8 + 4];
#pragma unroll
            for (int i = 0; i < 8; ++i)
#pragma unroll
                for (int j = 0; j < 8; ++j)
                    acc[i][j] = fmaf(a[i], b[j], acc[i][j]);
        }
        __syncthreads();
    }

    // epilogue: add biases, store
    float bv[8];
#pragma unroll
    for (int j = 0; j < 8; ++j) {
        int n = bn + tx * 8 + j;
        bv[j] = b1[n] + b2[n];
    }
#pragma unroll
    for (int i = 0; i < 8; ++i) {
        size_t off = (size_t)(bm + ty * 8 + i) * GROWS + bn + tx * 8;
        float4 o1, o2;
        o1.x = acc[i][0] + bv[0]; o1.y = acc[i][1] + bv[1];
        o1.z = acc[i][2] + bv[2]; o1.w = acc[i][3] + bv[3];
        o2.x = acc[i][4] + bv[4]; o2.y = acc[i][5] + bv[5];
        o2.z = acc[i][6] + bv[6]; o2.w = acc[i][7] + bv[7];
        *(float4*)&g_xg[off]     = o1;
        *(float4*)&g_xg[off + 4] = o2;
    }
}

// ============================================================================
// Kernel 2: persistent LSTM recurrence. 147 co-resident CTAs, W_hh (fp16) in
// SMEM, h broadcast via global + spin barrier each step, fp32 accumulation.
// CTA b owns hidden units [b*UPC, b*UPC+nu); rows r = gate*nu + u in SMEM.
// ============================================================================
__global__ void __launch_bounds__(RTHREADS, 1)
lstm_persistent(const float* __restrict__ W_hh)   // [GROWS][HDIM] fp32
{
    extern __shared__ __half sw[];            // [4*nu][HDIM] fp16 weights
    __shared__ float s_gate[MAXROWS];
    __shared__ float s_c[UPC];

    const int tid  = threadIdx.x;
    const int wid  = tid >> 5;
    const int lane = tid & 31;
    const int cta  = blockIdx.x;
    const int u0   = cta * UPC;
    const int nu   = (HDIM - u0 < UPC) ? (HDIM - u0) : UPC;
    const int nrows = 4 * nu;

    // ---- one-time: load W_hh rows for our units, convert fp32 -> fp16 ----
    for (int e = tid * 4; e < nrows * HDIM; e += RTHREADS * 4) {
        int r    = e / HDIM;
        int k    = e - r * HDIM;
        int gate = r / nu;
        int u    = r - gate * nu;
        const float4 v = *(const float4*)&W_hh[(size_t)(gate * HDIM + u0 + u) * HDIM + k];
        __half2* dst = (__half2*)&sw[r * HDIM + k];
        dst[0] = __floats2half2_rn(v.x, v.y);
        dst[1] = __floats2half2_rn(v.z, v.w);
    }
    if (tid < UPC)     s_c[tid]    = 0.f;
    if (tid < MAXROWS) s_gate[tid] = 0.f;

    unsigned base = 0u;
    if (tid == 0) base = *(volatile unsigned*)&g_base;
    __syncthreads();

    for (int t = 0; t < SEQ; ++t) {
        // prefetch this step's xg rows (independent of h -> hidden under barrier)
        float xgv0 = 0.f, xgv1 = 0.f, xgv2 = 0.f, xgv3 = 0.f;
        if (tid < nu) {
            const float* xp = g_xg + (size_t)t * GROWS + u0 + tid;
            xgv0 = xp[0 * HDIM];
            xgv1 = xp[1 * HDIM];
            xgv2 = xp[2 * HDIM];
            xgv3 = xp[3 * HDIM];
        }

        if (t > 0) {
            __syncthreads();   // (A) all of step t-1's h writes are CTA-ordered
            if (tid == 0) {
                __threadfence();                       // release our h writes
                atomicAdd(&g_bar, 1u);
                unsigned tgt = base + (unsigned)NCTA * (unsigned)t;
                while ((int)(*(volatile unsigned*)&g_bar - tgt) < 0) { }
                __threadfence();                       // acquire + CCTL.IVALL (fresh L1)
            }
            __syncthreads();   // (B) release all warps

            // ---- load full h (2048 fp32) into registers; L1-shared across warps ----
            float hreg[64];
            const float* hb = g_h[t & 1];
#pragma unroll
            for (int c = 0; c < 8; ++c) {
                const float4 v0 = *(const float4*)&hb[c * 256 + lane * 8];
                const float4 v1 = *(const float4*)&hb[c * 256 + lane * 8 + 4];
                hreg[c * 8 + 0] = v0.x; hreg[c * 8 + 1] = v0.y;
                hreg[c * 8 + 2] = v0.z; hreg[c * 8 + 3] = v0.w;
                hreg[c * 8 + 4] = v1.x; hreg[c * 8 + 5] = v1.y;
                hreg[c * 8 + 6] = v1.z; hreg[c * 8 + 7] = v1.w;
            }

            // ---- dot products: warp w handles rows w, w+8, ... ----
            for (int r = wid; r < nrows; r += 8) {
                const __half* wr = sw + r * HDIM;
                float a0 = 0.f, a1 = 0.f, a2 = 0.f, a3 = 0.f;
#pragma unroll
                for (int c = 0; c < 8; ++c) {
                    const uint4 wv = *(const uint4*)(wr + c * 256 + lane * 8);
                    const __half2 p0 = *reinterpret_cast<const __half2*>(&wv.x);
                    const __half2 p1 = *reinterpret_cast<const __half2*>(&wv.y);
                    const __half2 p2 = *reinterpret_cast<const __half2*>(&wv.z);
                    const __half2 p3 = *reinterpret_cast<const __half2*>(&wv.w);
                    float2 f;
                    f = __half22float2(p0);
                    a0 = fmaf(f.x, hreg[c * 8 + 0], a0);
                    a1 = fmaf(f.y, hreg[c * 8 + 1], a1);
                    f = __half22float2(p1);
                    a2 = fmaf(f.x, hreg[c * 8 + 2], a2);
                    a3 = fmaf(f.y, hreg[c * 8 + 3], a3);
                    f = __half22float2(p2);
                    a0 = fmaf(f.x, hreg[c * 8 + 4], a0);
                    a1 = fmaf(f.y, hreg[c * 8 + 5], a1);
                    f = __half22float2(p3);
                    a2 = fmaf(f.x, hreg[c * 8 + 6], a2);
                    a3 = fmaf(f.y, hreg[c * 8 + 7], a3);
                }
                float acc = (a0 + a1) + (a2 + a3);
#pragma unroll
                for (int off = 16; off; off >>= 1)
                    acc += __shfl_xor_sync(0xffffffffu, acc, off);
                if (lane == 0) s_gate[r] = acc;
            }
        }
        __syncthreads();

        // ---- gate combine + state update (CTA-local) ----
        if (tid < nu) {
            const float gi = xgv0 + s_gate[0 * nu + tid];
            const float gf = xgv1 + s_gate[1 * nu + tid];
            const float gg = xgv2 + s_gate[2 * nu + tid];
            const float go = xgv3 + s_gate[3 * nu + tid];
            const float ig = 1.f / (1.f + expf(-gi));
            const float fg = 1.f / (1.f + expf(-gf));
            const float g2 = tanhf(gg);
            const float og = 1.f / (1.f + expf(-go));
            const float cc = fg * s_c[tid] + ig * g2;
            s_c[tid] = cc;
            g_h[(t + 1) & 1][u0 + tid] = og * tanhf(cc);
        }
    }

    // final barrier: safe epoch-base update for the next graph replay
    __syncthreads();
    if (tid == 0) {
        __threadfence();
        atomicAdd(&g_bar, 1u);
        unsigned tgt = base + (unsigned)NCTA * (unsigned)SEQ;
        while ((int)(*(volatile unsigned*)&g_bar - tgt) < 0) { }
        if (cta == 0) *(volatile unsigned*)&g_base = tgt;
    }
}

// ============================================================================
// Kernel 3: out = h_last @ W_fc^T + b_fc   (h_last lives in g_h[0]; SEQ even)
// ============================================================================
__global__ void __launch_bounds__(256)
fc_kernel(const float* __restrict__ Wfc, const float* __restrict__ bfc,
          float* __restrict__ out)
{
    const int o    = blockIdx.x * 8 + (threadIdx.x >> 5);
    const int lane = threadIdx.x & 31;
    const float* hb = g_h[0];
    const float* wr = Wfc + (size_t)o * HDIM;
    float acc = 0.f;
#pragma unroll
    for (int i = 0; i < 16; ++i) {
        const int k = i * 128 + lane * 4;
        const float4 w  = *(const float4*)&wr[k];
        const float4 h4 = *(const float4*)&hb[k];
        acc += w.x * h4.x + w.y * h4.y + w.z * h4.z + w.w * h4.w;
    }
#pragma unroll
    for (int off = 16; off; off >>= 1)
        acc += __shfl_xor_sync(0xffffffffu, acc, off);
    if (lane == 0) out[o] = acc + bfc[o];
}

// ============================================================================
extern "C" void kernel_launch(void* const* d_in, const int* in_sizes, int n_in,
                              void* d_out, int out_size)
{
    const float* x   = (const float*)d_in[0];   // [1,4096,2048]
    const float* Wih = (const float*)d_in[1];   // [8192,2048]
    const float* Whh = (const float*)d_in[2];   // [8192,2048]
    const float* bih = (const float*)d_in[3];   // [8192]
    const float* bhh = (const float*)d_in[4];   // [8192]
    const float* Wfc = (const float*)d_in[5];   // [2048,2048]
    const float* bfc = (const float*)d_in[6];   // [2048]
    float* out = (float*)d_out;                 // [2048]

    cudaFuncSetAttribute(lstm_persistent,
                         cudaFuncAttributeMaxDynamicSharedMemorySize,
                         (int)SW_BYTES);

    gemm_xg_kernel<<<dim3(GROWS / 128, SEQ / 128), 256>>>(x, Wih, bih, bhh);
    lstm_persistent<<<NCTA, RTHREADS, SW_BYTES>>>(Whh);
    fc_kernel<<<OUTD / 8, 256>>>(Wfc, bfc, out);
}